// round 16
// baseline (speedup 1.0000x reference)
#include <cuda_runtime.h>
#include <cstdint>
#include <cstddef>

// Problem constants
#define BATCH 64
#define TT    512
#define HID   512
#define G4    2048          // 4*HID
#define CTX   792
#define IND   1048
#define VOCAB 260
#define BCL   8
#define BED   32

// ---------------- static device scratch (no runtime allocation) ----------------
__device__ float g_ctxT[CTX * BATCH];                 // context transposed [k][b]
__device__ float g_ctxg[G4 * BATCH];                  // W_ih0[:, :792]@ctx + b_ih0 + b_hh0, [row][b]
__device__ float g_proj[(size_t)BCL * G4 * VOCAB];    // [j][row][v]  (17 MB)
__device__ float g_gx[(size_t)TT * G4 * BATCH];       // input gates [t][row][b] (268 MB)
__device__ float g_h[(size_t)TT * HID * BATCH];       // h states [t][j][b] (64 MB)
__device__ float g_WoutT[HID * 256];                  // W_out transposed [k][v]
__device__ unsigned g_bar;                            // grid barrier counter

// ---------------- math helpers ----------------
__device__ __forceinline__ float sigm(float x) { return 1.0f / (1.0f + __expf(-x)); }
__device__ __forceinline__ float tanh_(float x) { return 2.0f / (1.0f + __expf(-2.0f * x)) - 1.0f; }

// packed f32x2 helpers (sm_103a double-rate fp32, PTX-only)
__device__ __forceinline__ void fma2(uint64_t& d, uint64_t a, uint64_t b) {
    asm("fma.rn.f32x2 %0, %1, %2, %0;" : "+l"(d) : "l"(a), "l"(b));
}
__device__ __forceinline__ uint64_t pack2(float lo, float hi) {
    uint64_t r; asm("mov.b64 %0, {%1, %2};" : "=l"(r) : "f"(lo), "f"(hi)); return r;
}
__device__ __forceinline__ float hsum2(uint64_t v) {
    float lo, hi; asm("mov.b64 {%0, %1}, %2;" : "=f"(lo), "=f"(hi) : "l"(v)); return lo + hi;
}

// ---------------- 1) build transposed context [792][64] ----------------
__global__ __launch_bounds__(256) void build_ctx(
    const float* __restrict__ ecc, const int* __restrict__ cat,
    const float* __restrict__ num, const float* __restrict__ e0,
    const float* __restrict__ e1, const float* __restrict__ e2)
{
    int idx = blockIdx.x * blockDim.x + threadIdx.x;   // 792*64 = 50688
    if (idx >= CTX * BATCH) return;
    int k = idx >> 6;
    int b = idx & 63;
    float v;
    if (k < 512)      v = ecc[b * 512 + k];
    else if (k < 562) v = e0[cat[b * 3 + 0] * 50  + (k - 512)];
    else if (k < 626) v = e1[cat[b * 3 + 1] * 64  + (k - 562)];
    else if (k < 776) v = e2[cat[b * 3 + 2] * 150 + (k - 626)];
    else              v = num[b * 16 + (k - 776)];
    g_ctxT[k * BATCH + b] = v;
}

// ---------------- 2) ctx gates: [2048][64] = W_ih0[:, :792] @ ctx + biases ----------------
__global__ __launch_bounds__(256) void ctx_gates_k(
    const float* __restrict__ Wih0, const float* __restrict__ bih0, const float* __restrict__ bhh0)
{
    int tid = threadIdx.x;
    int b = tid & 63, q = tid >> 6;
    int rbase = blockIdx.x * 32 + q * 8;   // 64 blocks * 32 rows
    float acc[8];
#pragma unroll
    for (int i = 0; i < 8; i++) acc[i] = bih0[rbase + i] + bhh0[rbase + i];
    for (int k = 0; k < CTX; k += 4) {
        float h0 = g_ctxT[(k + 0) * BATCH + b];
        float h1 = g_ctxT[(k + 1) * BATCH + b];
        float h2 = g_ctxT[(k + 2) * BATCH + b];
        float h3 = g_ctxT[(k + 3) * BATCH + b];
#pragma unroll
        for (int i = 0; i < 8; i++) {
            float4 w = *(const float4*)&Wih0[(size_t)(rbase + i) * IND + k];
            acc[i] += w.x * h0 + w.y * h1 + w.z * h2 + w.w * h3;
        }
    }
#pragma unroll
    for (int i = 0; i < 8; i++) g_ctxg[(rbase + i) * BATCH + b] = acc[i];
}

// ---------------- 3) proj[j][row][v] = W_ih0[row, 792+32j : +32] @ byte_emb[v] ----------------
__global__ __launch_bounds__(256) void proj_k(
    const float* __restrict__ Wih0, const float* __restrict__ bemb)
{
    __shared__ float emb_s[VOCAB * 33];
    __shared__ float Wc[8 * 32];
    int tid = threadIdx.x;
    int rowbase = blockIdx.x * 8;   // 256 row-tiles
    int j = blockIdx.y;             // 8
    for (int i = tid; i < VOCAB * BED; i += 256) {
        int v = i >> 5, k = i & 31;
        emb_s[v * 33 + k] = bemb[i];
    }
    if (tid < 256) {
        int r = tid >> 5, k = tid & 31;
        Wc[tid] = Wih0[(size_t)(rowbase + r) * IND + CTX + 32 * j + k];
    }
    __syncthreads();
    for (int v = tid; v < VOCAB; v += 256) {
#pragma unroll
        for (int r = 0; r < 8; r++) {
            float a = 0.f;
#pragma unroll
            for (int k = 0; k < 32; k++) a += Wc[r * 32 + k] * emb_s[v * 33 + k];
            g_proj[((size_t)j * G4 + rowbase + r) * VOCAB + v] = a;
        }
    }
}

// ---------------- 4) assemble gx0[t][row][b] ----------------
__global__ __launch_bounds__(256) void gx0_assemble(const int* __restrict__ payload)
{
    int t = blockIdx.y;
    int rowTile = blockIdx.x;   // 32 tiles of 64 rows
    __shared__ int sb[BATCH * BCL];
    int tid = threadIdx.x;
    for (int idx = tid; idx < BATCH * BCL; idx += 256) {
        int bb = idx >> 3, j = idx & 7;
        int p = t + j;
        int v = (p < 7) ? 256 : ((p == 7) ? 257 : payload[bb * TT + p - 8]);
        sb[idx] = v;
    }
    __syncthreads();
    int b = tid & 63, rq = tid >> 6;
    int vb[8];
#pragma unroll
    for (int j = 0; j < 8; j++) vb[j] = sb[b * 8 + j];
    int rbase = rowTile * 64 + rq * 16;
    for (int rr = 0; rr < 16; rr++) {
        int row = rbase + rr;
        float acc = g_ctxg[row * BATCH + b];
#pragma unroll
        for (int j = 0; j < 8; j++)
            acc += __ldg(&g_proj[((size_t)j * G4 + row) * VOCAB + vb[j]]);
        g_gx[(size_t)t * (G4 * BATCH) + row * BATCH + b] = acc;
    }
}

// ---------------- 5) barrier reset ----------------
__global__ void reset_bar_k() { g_bar = 0u; }

// ---------------- 6) persistent LSTM recurrence: one launch = 512 steps ----------------
// grid 128, block 256; all blocks co-resident. CG-style barrier: bar.sync +
// one red.release.gpu arrive + ld.acquire.gpu spin with nanosleep backoff.
// Matvec uses packed fma.rn.f32x2 (double-rate fp32).
__global__ __launch_bounds__(256) void lstm_seq(const float* __restrict__ Whh)
{
    __shared__ __align__(16) float Ws[16 * HID];   // 16 gate-rows x 512 = 32 KB
    int tid = threadIdx.x;
    int b = tid & 63, q = tid >> 6;
    int j = blockIdx.x * 4 + q;

    // stage W rows {gate*512 + blockIdx.x*4 + qq} into smem (once per launch)
    for (int f = tid; f < 2048; f += 256) {          // 2048 float4
        int r16 = f >> 7;
        int kk = (f & 127) * 4;
        int gate = r16 >> 2, qq = r16 & 3;
        *(float4*)&Ws[r16 * HID + kk] =
            *(const float4*)&Whh[(size_t)(gate * HID + blockIdx.x * 4 + qq) * HID + kk];
    }
    __syncthreads();

    const float* Wi = &Ws[(0 * 4 + q) * HID];
    const float* Wf = &Ws[(1 * 4 + q) * HID];
    const float* Wg = &Ws[(2 * 4 + q) * HID];
    const float* Wo = &Ws[(3 * 4 + q) * HID];

    float c = 0.f;

    // prefetch input-gate contributions for t=0
    float gi = __ldg(&g_gx[(0 * HID + j) * BATCH + b]);
    float gf = __ldg(&g_gx[(1 * HID + j) * BATCH + b]);
    float gg = __ldg(&g_gx[(2 * HID + j) * BATCH + b]);
    float go = __ldg(&g_gx[(3 * HID + j) * BATCH + b]);

    for (int t = 0; t < TT; t++) {
        if (t > 0) {
            const float* hprev = g_h + (size_t)(t - 1) * (HID * BATCH);
            uint64_t aI = 0ull, aF = 0ull, aG = 0ull, aO = 0ull;  // {0.f,0.f}
#pragma unroll 4
            for (int k = 0; k < HID; k += 4) {
                float h0 = __ldg(&hprev[(k + 0) * BATCH + b]);
                float h1 = __ldg(&hprev[(k + 1) * BATCH + b]);
                float h2 = __ldg(&hprev[(k + 2) * BATCH + b]);
                float h3 = __ldg(&hprev[(k + 3) * BATCH + b]);
                uint64_t h01 = pack2(h0, h1);
                uint64_t h23 = pack2(h2, h3);
                ulonglong2 wi = *(const ulonglong2*)&Wi[k];
                ulonglong2 wf = *(const ulonglong2*)&Wf[k];
                ulonglong2 wg = *(const ulonglong2*)&Wg[k];
                ulonglong2 wo = *(const ulonglong2*)&Wo[k];
                fma2(aI, wi.x, h01); fma2(aF, wf.x, h01);
                fma2(aG, wg.x, h01); fma2(aO, wo.x, h01);
                fma2(aI, wi.y, h23); fma2(aF, wf.y, h23);
                fma2(aG, wg.y, h23); fma2(aO, wo.y, h23);
            }
            gi += hsum2(aI); gf += hsum2(aF);
            gg += hsum2(aG); go += hsum2(aO);
        }

        float si = sigm(gi), sf = sigm(gf), so = sigm(go);
        float tg = tanh_(gg);
        c = sf * c + si * tg;
        float h = so * tanh_(c);
        g_h[(size_t)t * (HID * BATCH) + j * BATCH + b] = h;

        // prefetch next step's input gates (in flight across the barrier)
        float ngi = 0.f, ngf = 0.f, ngg = 0.f, ngo = 0.f;
        if (t + 1 < TT) {
            size_t gxn = (size_t)(t + 1) * (G4 * BATCH);
            ngi = __ldg(&g_gx[gxn + (0 * HID + j) * BATCH + b]);
            ngf = __ldg(&g_gx[gxn + (1 * HID + j) * BATCH + b]);
            ngg = __ldg(&g_gx[gxn + (2 * HID + j) * BATCH + b]);
            ngo = __ldg(&g_gx[gxn + (3 * HID + j) * BATCH + b]);
        }

        if (t < TT - 1) {
            __syncthreads();                       // all h stores issued, block-ordered
            if (tid == 0) {
                // release-arrive (REDG, no return), then acquire-spin with backoff
                asm volatile("red.release.gpu.add.u32 [%0], 1;"
                             :: "l"(&g_bar) : "memory");
                unsigned target = (unsigned)(t + 1) * 128u;
                unsigned v;
                while (true) {
                    asm volatile("ld.acquire.gpu.u32 %0, [%1];"
                                 : "=r"(v) : "l"(&g_bar) : "memory");
                    if (v >= target) break;
                    __nanosleep(32);
                }
            }
            __syncthreads();                       // acquire propagated block-wide
        }
        gi = ngi; gf = ngf; gg = ngg; go = ngo;
    }
}

// ---------------- 7) gx1[t][row][b] = W_ih1 @ h1[t] + (b_ih1 + b_hh1) ----------------
__global__ __launch_bounds__(256) void gx1_k(
    const float* __restrict__ Wih1, const float* __restrict__ bih1, const float* __restrict__ bhh1)
{
    int t = blockIdx.y;
    int tile = blockIdx.x;     // 64 tiles * 32 rows
    int tid = threadIdx.x;
    int b = tid & 63, q = tid >> 6;
    int rbase = tile * 32 + q * 8;
    const float* ht = g_h + (size_t)t * (HID * BATCH);
    uint64_t acc[8];
#pragma unroll
    for (int i = 0; i < 8; i++) acc[i] = 0ull;
    for (int k = 0; k < HID; k += 4) {
        float h0 = __ldg(&ht[(k + 0) * BATCH + b]);
        float h1 = __ldg(&ht[(k + 1) * BATCH + b]);
        float h2 = __ldg(&ht[(k + 2) * BATCH + b]);
        float h3 = __ldg(&ht[(k + 3) * BATCH + b]);
        uint64_t h01 = pack2(h0, h1);
        uint64_t h23 = pack2(h2, h3);
#pragma unroll
        for (int i = 0; i < 8; i++) {
            ulonglong2 w = *(const ulonglong2*)&Wih1[(size_t)(rbase + i) * HID + k];
            fma2(acc[i], w.x, h01);
            fma2(acc[i], w.y, h23);
        }
    }
#pragma unroll
    for (int i = 0; i < 8; i++)
        g_gx[(size_t)t * (G4 * BATCH) + (rbase + i) * BATCH + b] =
            hsum2(acc[i]) + bih1[rbase + i] + bhh1[rbase + i];
}

// ---------------- 8) transpose W_out [256][512] -> [512][256] ----------------
__global__ void transpose_wout(const float* __restrict__ W)
{
    __shared__ float tile[32][33];
    int bx = blockIdx.x;   // 16 k-tiles
    int by = blockIdx.y;   // 8 v-tiles
    int x = bx * 32 + threadIdx.x;  // k
    int y = by * 32 + threadIdx.y;  // v
    tile[threadIdx.y][threadIdx.x] = W[y * 512 + x];
    __syncthreads();
    g_WoutT[(bx * 32 + threadIdx.y) * 256 + by * 32 + threadIdx.x] = tile[threadIdx.x][threadIdx.y];
}

// ---------------- 9) output projection: logits[b][t][v] ----------------
__global__ __launch_bounds__(256) void out_k(const float* __restrict__ bout, float* __restrict__ out)
{
    int t = blockIdx.x;
    int v = threadIdx.x;     // 256
    const float* ht = g_h + (size_t)t * (HID * BATCH);
    float acc[64];
#pragma unroll
    for (int i = 0; i < 64; i++) acc[i] = 0.f;
    for (int k = 0; k < HID; k++) {
        float w = __ldg(&g_WoutT[k * 256 + v]);
        const float4* h4p = (const float4*)&ht[k * BATCH];
#pragma unroll
        for (int bb = 0; bb < 16; bb++) {
            float4 h4 = __ldg(&h4p[bb]);
            acc[bb * 4 + 0] += w * h4.x;
            acc[bb * 4 + 1] += w * h4.y;
            acc[bb * 4 + 2] += w * h4.z;
            acc[bb * 4 + 3] += w * h4.w;
        }
    }
    float bo = bout[v];
#pragma unroll
    for (int b = 0; b < 64; b++)
        out[((size_t)b * TT + t) * 256 + v] = acc[b] + bo;
}

// ---------------- launch ----------------
extern "C" void kernel_launch(void* const* d_in, const int* in_sizes, int n_in,
                              void* d_out, int out_size)
{
    const float* ecc     = (const float*)d_in[0];
    const int*   cat     = (const int*)  d_in[1];
    const float* num     = (const float*)d_in[2];
    const int*   payload = (const int*)  d_in[3];
    const float* e0      = (const float*)d_in[4];
    const float* e1      = (const float*)d_in[5];
    const float* e2      = (const float*)d_in[6];
    const float* bemb    = (const float*)d_in[7];
    const float* Wih0    = (const float*)d_in[8];
    const float* Whh0    = (const float*)d_in[9];
    const float* bih0    = (const float*)d_in[10];
    const float* bhh0    = (const float*)d_in[11];
    const float* Wih1    = (const float*)d_in[12];
    const float* Whh1    = (const float*)d_in[13];
    const float* bih1    = (const float*)d_in[14];
    const float* bhh1    = (const float*)d_in[15];
    const float* Wout    = (const float*)d_in[16];
    const float* bout    = (const float*)d_in[17];
    float* out = (float*)d_out;

    // parallel precompute
    build_ctx<<<198, 256>>>(ecc, cat, num, e0, e1, e2);
    ctx_gates_k<<<64, 256>>>(Wih0, bih0, bhh0);
    proj_k<<<dim3(256, 8), 256>>>(Wih0, bemb);
    transpose_wout<<<dim3(16, 8), dim3(32, 32)>>>(Wout);
    gx0_assemble<<<dim3(32, TT), 256>>>(payload);

    // layer 0 recurrence (single persistent launch)
    reset_bar_k<<<1, 1>>>();
    lstm_seq<<<128, 256>>>(Whh0);

    // layer 1 input gates (parallel GEMM), then layer 1 recurrence
    gx1_k<<<dim3(64, TT), 256>>>(Wih1, bih1, bhh1);
    reset_bar_k<<<1, 1>>>();
    lstm_seq<<<128, 256>>>(Whh1);

    // output head
    out_k<<<TT, 256>>>(bout, out);
}